// round 2
// baseline (speedup 1.0000x reference)
#include <cuda_runtime.h>

#define BATCH 1024
#define NB 8            // batches per block
#define NTH 512         // threads per block: 1 gate row each
#define HID 128
#define G4  512         // 4*HID gate rows
#define KS  80          // W_hh cols cached in smem
#define KSP 84          // padded smem row stride (conflict-free LDS.128)
#define GP  10          // gates smem row stride
#define DTC 0.1f
#define Q0V 0.01f
#define RV  0.25f
#define FULL 0xffffffffu

// shared memory layout (float offsets)
#define O_WHH   0                      // 512*84 = 43008
#define O_GATES 43008                  // 512*10 = 5120
#define O_H     48128                  // 128*8  = 1024   (h stored [k][b])
#define O_WIH   49152                  // 1024
#define O_BIAS  50176                  // 512 (b_ih+b_hh)
#define O_WFCP  50688                  // 10*132 = 1320 (padded, conflict-free)
#define O_QT    52008                  // 160
#define O_IN    52168                  // 16
#define O_BFC   52184                  // 10
#define SMEM_FLOATS 52200
#define SMEM_BYTES (SMEM_FLOATS * 4)   // 208,800 B < 227KB

typedef unsigned long long ull;

__device__ __forceinline__ float tanh_ap(float x) {
    float y; asm("tanh.approx.f32 %0, %1;" : "=f"(y) : "f"(x)); return y;
}
__device__ __forceinline__ float sigm(float x) {
    return fmaf(tanh_ap(0.5f * x), 0.5f, 0.5f);
}
__device__ __forceinline__ ull pk2(float x) {
    ull r; asm("mov.b64 %0, {%1, %1};" : "=l"(r) : "f"(x)); return r;
}
__device__ __forceinline__ ull pkab(float lo, float hi) {
    ull r; asm("mov.b64 %0, {%1, %2};" : "=l"(r) : "f"(lo), "f"(hi)); return r;
}
#define FMA2(acc, w, h) asm("fma.rn.f32x2 %0, %1, %2, %0;" : "+l"(acc) : "l"(w), "l"(h))

// Warp-parallel Kalman predict + innovation for step t (warp = one batch).
// Lane e (e<16) holds P element e. All lanes get xp*, iv*; Pp is lane-distributed.
__device__ __forceinline__ void kpredict(
    float& Pp, float& xp0, float& xp1, float& xp2, float& xp3,
    float& iv0, float& iv1,
    float P, float x0, float x1, float x2, float x3,
    const float* __restrict__ meas, float* smem,
    size_t gb, int t, int T, int lane, int b)
{
    xp0 = fmaf(DTC, x2, x0); xp1 = fmaf(DTC, x3, x1); xp2 = x2; xp3 = x3;
    // A = F*P  (A[i][j] = P[i][j] + DT*P[i+2][j] for i<2)
    float P8 = __shfl_down_sync(FULL, P, 8);
    float A  = (lane < 8) ? fmaf(DTC, P8, P) : P;
    // Pp = A*F^T (Pp[i][j] = A[i][j] + DT*A[i][j+2] for j<2), + Q0 diag
    float A2 = __shfl_down_sync(FULL, A, 2);
    float Ppv = ((lane & 3) < 2) ? fmaf(DTC, A2, A) : A;
    if (lane == 0 || lane == 5 || lane == 10 || lane == 15) Ppv += Q0V;
    Pp = Ppv;
    if (t < T) {
        float2 z = *(const float2*)(meas + ((size_t)gb * T + t) * 2);
        iv0 = z.x - xp0; iv1 = z.y - xp1;
        float Pp0 = __shfl_sync(FULL, Ppv, 0);
        float Pp5 = __shfl_sync(FULL, Ppv, 5);
        if (lane == 0) {
            smem[O_IN + 2 * b]     = iv0 * iv0 / (Pp0 + RV);
            smem[O_IN + 2 * b + 1] = iv1 * iv1 / (Pp5 + RV);
        }
    }
}

__global__ void __launch_bounds__(NTH, 1) nnakf_kernel(
    const float* __restrict__ meas, const float* __restrict__ Qt,
    const float* __restrict__ Wih,  const float* __restrict__ Whh,
    const float* __restrict__ bih,  const float* __restrict__ bhh,
    const float* __restrict__ Wfc,  const float* __restrict__ bfc,
    float* __restrict__ out, int T)
{
    extern __shared__ float smem[];
    const int tid  = threadIdx.x;
    const int wid  = tid >> 5;
    const int lane = tid & 31;

    // ---- one-time setup: stage weights in smem ----
    for (int idx = tid; idx < G4 * KS; idx += NTH) {
        int r = idx / KS, c = idx - r * KS;
        smem[O_WHH + r * KSP + c] = Whh[r * HID + c];
    }
    for (int idx = tid; idx < G4 * 2; idx += NTH) smem[O_WIH + idx] = Wih[idx];
    for (int idx = tid; idx < G4;     idx += NTH) smem[O_BIAS + idx] = bih[idx] + bhh[idx];
    for (int idx = tid; idx < 10*HID; idx += NTH) {
        int n = idx >> 7, k = idx & 127;
        smem[O_WFCP + n * 132 + k] = Wfc[idx];
    }
    for (int idx = tid; idx < 160;    idx += NTH) smem[O_QT + idx] = Qt[idx];
    if (tid < 10) smem[O_BFC + tid] = bfc[tid];
    for (int idx = tid; idx < HID*NB; idx += NTH) smem[O_H + idx] = 0.0f;
    __syncthreads();

    // ---- per-thread GEMV constants (row r = tid) ----
    const int r = tid;
    const float rb  = smem[O_BIAS + r];
    const float wi0 = smem[O_WIH + 2*r], wi1 = smem[O_WIH + 2*r + 1];

    float creg[2] = {0.f, 0.f};                 // LSTM c state (2 (hid,b) items)

    // ---- Kalman lane state (warps 0..7, lanes 0..15 hold P element e) ----
    float P = (lane == 0 || lane == 5 || lane == 10 || lane == 15) ? 1.0f : 0.0f;
    float x0 = 0.f, x1 = 0.f, x2 = 0.f, x3 = 0.f;
    float Pp = 0.f, xp0 = 0.f, xp1 = 0.f, xp2 = 0.f, xp3 = 0.f, iv0 = 0.f, iv1 = 0.f;
    const size_t gb = (size_t)blockIdx.x * NB + wid;

    if (wid < NB)
        kpredict(Pp, xp0, xp1, xp2, xp3, iv0, iv1, P, x0, x1, x2, x3,
                 meas, smem, gb, 0, T, lane, wid);
    __syncthreads();

    for (int t = 0; t < T; t++) {
        // ---- Phase A: gates = In@Wih^T + bias + h@Whh^T (f32x2 packed) ----
        ull a0, a1, a2, a3;
        {
            float s[NB];
            #pragma unroll
            for (int b = 0; b < NB; b++) {
                float i0 = smem[O_IN + 2*b], i1 = smem[O_IN + 2*b + 1];
                s[b] = fmaf(wi1, i1, fmaf(wi0, i0, rb));
            }
            a0 = pkab(s[0], s[1]); a1 = pkab(s[2], s[3]);
            a2 = pkab(s[4], s[5]); a3 = pkab(s[6], s[7]);
        }
        #pragma unroll
        for (int kc = 0; kc < HID / 4; kc++) {
            const int k = kc * 4;
            float4 w;
            if (k < KS) {   // compile-time resolved under full unroll
                w = *(const float4*)&smem[O_WHH + r * KSP + k];
            } else {
                w = __ldg((const float4*)(Whh + r * HID + k));
            }
            #pragma unroll
            for (int u = 0; u < 4; u++) {
                ull wp = pk2((&w.x)[u]);
                ulonglong2 ha = *(const ulonglong2*)&smem[O_H + (k + u) * NB];
                ulonglong2 hb = *(const ulonglong2*)&smem[O_H + (k + u) * NB + 4];
                FMA2(a0, wp, ha.x); FMA2(a1, wp, ha.y);
                FMA2(a2, wp, hb.x); FMA2(a3, wp, hb.y);
            }
        }
        {
            ull* g = (ull*)&smem[O_GATES + r * GP];
            g[0] = a0; g[1] = a1; g[2] = a2; g[3] = a3;
        }
        __syncthreads();

        // ---- Phase A2: c/h update (1024 items / 512 threads) ----
        #pragma unroll
        for (int q = 0; q < 2; q++) {
            int m = q * NTH + tid;
            int hid = m & (HID - 1), b = m >> 7;
            float gi = smem[O_GATES + hid * GP + b];
            float gf = smem[O_GATES + (HID + hid) * GP + b];
            float gg = smem[O_GATES + (2*HID + hid) * GP + b];
            float go = smem[O_GATES + (3*HID + hid) * GP + b];
            float c = sigm(gf) * creg[q] + sigm(gi) * tanh_ap(gg);
            creg[q] = c;
            smem[O_H + hid * NB + b] = sigm(go) * tanh_ap(c);
        }
        __syncthreads();

        // ---- Phase C (warps 0..7): sigma-FC + Q-adapt + update + predict(t+1) ----
        if (wid < NB) {
            // sigma: lanes 0..9, one FC row each
            float sg = 0.0f;
            if (lane < 10) {
                const float* wf = &smem[O_WFCP + lane * 132];
                float q0 = smem[O_BFC + lane], q1 = 0.f, q2 = 0.f, q3 = 0.f;
                #pragma unroll
                for (int k = 0; k < HID; k += 4) {
                    q0 = fmaf(smem[O_H + (k+0) * NB + wid], wf[k+0], q0);
                    q1 = fmaf(smem[O_H + (k+1) * NB + wid], wf[k+1], q1);
                    q2 = fmaf(smem[O_H + (k+2) * NB + wid], wf[k+2], q2);
                    q3 = fmaf(smem[O_H + (k+3) * NB + wid], wf[k+3], q3);
                }
                sg = sigm((q0 + q1) + (q2 + q3));
            }
            // Q-adapt: Pp[e] += sum_n sigma_n * Qt[n][e]
            float Ppl = Pp;
            #pragma unroll
            for (int n = 0; n < 10; n++) {
                float sn = __shfl_sync(FULL, sg, n);
                Ppl = fmaf(sn, smem[O_QT + n * 16 + (lane & 15)], Ppl);
            }
            // S (post-adapt), gain, update
            float s00 = __shfl_sync(FULL, Ppl, 0) + RV;
            float s01 = __shfl_sync(FULL, Ppl, 1);
            float s10 = __shfl_sync(FULL, Ppl, 4);
            float s11 = __shfl_sync(FULL, Ppl, 5) + RV;
            float rdet = 1.0f / (s00 * s11 - s01 * s10);
            int i4 = lane & 12, j = lane & 3;
            float Pp4i  = __shfl_sync(FULL, Ppl, i4);
            float Pp4i1 = __shfl_sync(FULL, Ppl, i4 + 1);
            float Ppj   = __shfl_sync(FULL, Ppl, j);
            float Pp4j  = __shfl_sync(FULL, Ppl, 4 + j);
            float K0 = (Pp4i * s11 - Pp4i1 * s10) * rdet;
            float K1 = (Pp4i1 * s00 - Pp4i * s01) * rdet;
            P = Ppl - K0 * Ppj - K1 * Pp4j;          // new P (lanes < 16)
            // x update on lanes 0,4,8,12 (i = lane>>2)
            float xpi = (lane >= 8) ? ((lane >= 12) ? xp3 : xp2)
                                    : ((lane >= 4) ? xp1 : xp0);
            float xn = xpi + K0 * iv0 + K1 * iv1;
            if ((lane & 3) == 0 && lane < 16)
                out[((size_t)gb * T + t) * 4 + (lane >> 2)] = xn;
            x0 = __shfl_sync(FULL, xn, 0);
            x1 = __shfl_sync(FULL, xn, 4);
            x2 = __shfl_sync(FULL, xn, 8);
            x3 = __shfl_sync(FULL, xn, 12);
            // predict for t+1 (writes In for next Phase A)
            kpredict(Pp, xp0, xp1, xp2, xp3, iv0, iv1, P, x0, x1, x2, x3,
                     meas, smem, gb, t + 1, T, lane, wid);
        }
        __syncthreads();
    }
}

extern "C" void kernel_launch(void* const* d_in, const int* in_sizes, int n_in,
                              void* d_out, int out_size) {
    const float* meas = (const float*)d_in[0];
    const float* Qt   = (const float*)d_in[1];
    const float* Wih  = (const float*)d_in[2];
    const float* Whh  = (const float*)d_in[3];
    const float* bih  = (const float*)d_in[4];
    const float* bhh  = (const float*)d_in[5];
    const float* Wfc  = (const float*)d_in[6];
    const float* bfc  = (const float*)d_in[7];
    float* out = (float*)d_out;
    int T = in_sizes[0] / (BATCH * 2);   // 512 for the reference shapes

    cudaFuncSetAttribute(nnakf_kernel,
                         cudaFuncAttributeMaxDynamicSharedMemorySize, SMEM_BYTES);
    nnakf_kernel<<<BATCH / NB, NTH, SMEM_BYTES>>>(
        meas, Qt, Wih, Whh, bih, bhh, Wfc, bfc, out, T);
}

// round 4
// speedup vs baseline: 3.8395x; 3.8395x over previous
#include <cuda_runtime.h>
#include <cuda_bf16.h>
#include <cstdint>

#define BATCH 1024
#define NB 8            // batches per CTA (MMA N)
#define NTH 512         // 16 warps
#define HID 128
#define G4  512
#define DTC 0.1f
#define Q0V 0.01f
#define RV  0.25f
#define FULL 0xffffffffu
#define HP  9           // padded stride for h-f32 / gate planes
#define GPL 1152        // floats per gate plane (128*9)
#define AST 272         // Whh bf16 row stride in bytes (136 bf16, conflict-free LDSM)

// ---- byte offsets in dynamic smem ----
#define O_A     0         // Whh bf16 [512 rows x 272B] = 139264
#define O_BF    139264    // B fragments (h bf16), 8 ksteps x 256B = 2048
#define O_GPL   141312    // 4 gate planes x 1152 floats = 18432
#define O_H     159744    // h f32 [k][HP] = 4608
#define O_WFCP  164352    // 10 x 132 floats = 5280
#define O_QT    169632    // 160 floats
#define O_IN    170272    // 16 floats
#define O_BFC   170336    // 10 floats
#define O_BIAS  170376    // 512 floats (b_ih + b_hh)
#define O_WIH   172424    // 1024 floats
#define SMEM_BYTES 176520

#define FI_GPL  (O_GPL / 4)
#define FI_H    (O_H / 4)
#define FI_WFCP (O_WFCP / 4)
#define FI_QT   (O_QT / 4)
#define FI_IN   (O_IN / 4)
#define FI_BFC  (O_BFC / 4)
#define FI_BIAS (O_BIAS / 4)
#define FI_WIH  (O_WIH / 4)

__device__ __forceinline__ uint32_t smem_u32(const void* p) {
    uint32_t a;
    asm("{ .reg .u64 t; cvta.to.shared.u64 t, %1; cvt.u32.u64 %0, t; }" : "=r"(a) : "l"(p));
    return a;
}
__device__ __forceinline__ float tanh_ap(float x) {
    float y; asm("tanh.approx.f32 %0, %1;" : "=f"(y) : "f"(x)); return y;
}
__device__ __forceinline__ float sigm(float x) {
    return fmaf(tanh_ap(0.5f * x), 0.5f, 0.5f);
}
__device__ __forceinline__ void ldsm4(uint32_t* a, uint32_t addr) {
    asm volatile("ldmatrix.sync.aligned.m8n8.x4.shared.b16 {%0,%1,%2,%3}, [%4];"
                 : "=r"(a[0]), "=r"(a[1]), "=r"(a[2]), "=r"(a[3]) : "r"(addr));
}
__device__ __forceinline__ void mma16816(float* c, const uint32_t* a, uint32_t b0, uint32_t b1) {
    asm volatile(
        "mma.sync.aligned.m16n8k16.row.col.f32.bf16.bf16.f32 "
        "{%0,%1,%2,%3}, {%4,%5,%6,%7}, {%8,%9}, {%0,%1,%2,%3};"
        : "+f"(c[0]), "+f"(c[1]), "+f"(c[2]), "+f"(c[3])
        : "r"(a[0]), "r"(a[1]), "r"(a[2]), "r"(a[3]), "r"(b0), "r"(b1));
}

// Warp-parallel Kalman predict + innovation (warp = one batch, lane e<16 = P elem e)
__device__ __forceinline__ void kpredict(
    float& Pp, float& xp0, float& xp1, float& xp2, float& xp3,
    float& iv0, float& iv1,
    float P, float x0, float x1, float x2, float x3,
    const float* __restrict__ meas, float* smf,
    size_t gb, int t, int T, int lane, int b)
{
    xp0 = fmaf(DTC, x2, x0); xp1 = fmaf(DTC, x3, x1); xp2 = x2; xp3 = x3;
    float P8 = __shfl_down_sync(FULL, P, 8);
    float A  = (lane < 8) ? fmaf(DTC, P8, P) : P;
    float A2 = __shfl_down_sync(FULL, A, 2);
    float Ppv = ((lane & 3) < 2) ? fmaf(DTC, A2, A) : A;
    if (lane == 0 || lane == 5 || lane == 10 || lane == 15) Ppv += Q0V;
    Pp = Ppv;
    if (t < T) {
        float2 z = *(const float2*)(meas + ((size_t)gb * T + t) * 2);
        iv0 = z.x - xp0; iv1 = z.y - xp1;
        float Pp0 = __shfl_sync(FULL, Ppv, 0);
        float Pp5 = __shfl_sync(FULL, Ppv, 5);
        if (lane == 0) {
            smf[FI_IN + 2 * b]     = iv0 * iv0 / (Pp0 + RV);
            smf[FI_IN + 2 * b + 1] = iv1 * iv1 / (Pp5 + RV);
        }
    }
}

__global__ void __launch_bounds__(NTH, 1) nnakf_kernel(
    const float* __restrict__ meas, const float* __restrict__ Qt,
    const float* __restrict__ Wih,  const float* __restrict__ Whh,
    const float* __restrict__ bih,  const float* __restrict__ bhh,
    const float* __restrict__ Wfc,  const float* __restrict__ bfc,
    float* __restrict__ out, int T)
{
    extern __shared__ char smem[];
    float* smf = (float*)smem;
    const uint32_t sb = smem_u32(smem);
    const int tid  = threadIdx.x;
    const int wid  = tid >> 5;
    const int lane = tid & 31;
    const int wg   = wid >> 2;          // gate class of this warp's rows (i,f,g,o)

    // ---- one-time staging ----
    for (int idx = tid; idx < G4 * HID; idx += NTH) {
        int r = idx >> 7, k = idx & 127;
        *(__nv_bfloat16*)(smem + O_A + r * AST + k * 2) = __float2bfloat16(Whh[idx]);
    }
    for (int i = tid; i < 2048 / 4; i += NTH) *(uint32_t*)(smem + O_BF + i * 4) = 0u;
    for (int idx = tid; idx < 10 * HID; idx += NTH) {
        int n = idx >> 7, k = idx & 127;
        smf[FI_WFCP + n * 132 + k] = Wfc[idx];
    }
    for (int idx = tid; idx < 160; idx += NTH) smf[FI_QT + idx] = Qt[idx];
    if (tid < 10) smf[FI_BFC + tid] = bfc[tid];
    for (int idx = tid; idx < G4; idx += NTH) smf[FI_BIAS + idx] = bih[idx] + bhh[idx];
    for (int idx = tid; idx < G4 * 2; idx += NTH) smf[FI_WIH + idx] = Wih[idx];
    __syncthreads();

    // ---- per-thread epilogue constants: rows R = w*32 + g + {0,8,16,24} ----
    const int g = lane >> 2, tq = lane & 3;
    const int rbase = wid * 32 + g;
    float bia[4], wa[4], wb[4];
    #pragma unroll
    for (int o = 0; o < 4; o++) {
        int r = rbase + o * 8;
        bia[o] = smf[FI_BIAS + r];
        wa[o]  = smf[FI_WIH + 2 * r];
        wb[o]  = smf[FI_WIH + 2 * r + 1];
    }
    // LDSM base addresses (invariant): tile0 rows rbase..(+8 via lane>>3 bit), k-half via lane>>4
    const int r_lds = (wid * 32) + (lane & 7) + ((lane >> 3) & 1) * 8;
    const uint32_t aA0 = sb + O_A + r_lds * AST + (lane >> 4) * 16;
    const uint32_t aA1 = aA0 + 16 * AST;
    const uint32_t aB  = sb + O_BF + lane * 4;

    float acc0[4] = {0.f, 0.f, 0.f, 0.f}, acc1[4] = {0.f, 0.f, 0.f, 0.f};
    float creg[2] = {0.f, 0.f};

    // ---- Kalman lane state (warps 0..7) ----
    float P = (lane == 0 || lane == 5 || lane == 10 || lane == 15) ? 1.0f : 0.0f;
    float x0 = 0.f, x1 = 0.f, x2 = 0.f, x3 = 0.f;
    float Pp = 0.f, xp0 = 0.f, xp1 = 0.f, xp2 = 0.f, xp3 = 0.f, iv0 = 0.f, iv1 = 0.f;
    const size_t gb = (size_t)blockIdx.x * NB + wid;

    if (wid < NB)
        kpredict(Pp, xp0, xp1, xp2, xp3, iv0, iv1, P, x0, x1, x2, x3,
                 meas, smf, gb, 0, T, lane, wid);
    __syncthreads();   // In(0) visible; accs=0 == gates from h0=0

    for (int t = 0; t < T; t++) {
        // ---- 1. epilogue: accs (gates pre-activation, MMA part) + In/bias, nonlin ----
        {
            float4 inv = *(const float4*)&smf[FI_IN + 4 * tq];  // In[2c0..2c0+3]
            float gv[8];
            gv[0] = fmaf(wa[0], inv.x, fmaf(wb[0], inv.y, acc0[0] + bia[0]));
            gv[1] = fmaf(wa[0], inv.z, fmaf(wb[0], inv.w, acc0[1] + bia[0]));
            gv[2] = fmaf(wa[1], inv.x, fmaf(wb[1], inv.y, acc0[2] + bia[1]));
            gv[3] = fmaf(wa[1], inv.z, fmaf(wb[1], inv.w, acc0[3] + bia[1]));
            gv[4] = fmaf(wa[2], inv.x, fmaf(wb[2], inv.y, acc1[0] + bia[2]));
            gv[5] = fmaf(wa[2], inv.z, fmaf(wb[2], inv.w, acc1[1] + bia[2]));
            gv[6] = fmaf(wa[3], inv.x, fmaf(wb[3], inv.y, acc1[2] + bia[3]));
            gv[7] = fmaf(wa[3], inv.z, fmaf(wb[3], inv.w, acc1[3] + bia[3]));
            #pragma unroll
            for (int u = 0; u < 8; u++)
                gv[u] = (wg == 2) ? tanh_ap(gv[u]) : sigm(gv[u]);
            const int hb = (wid & 3) * 32 + g;       // hid base (row mod 128)
            const int c0 = 2 * tq;
            float* pl = smf + FI_GPL + wg * GPL;
            pl[(hb +  0) * HP + c0]     = gv[0];
            pl[(hb +  0) * HP + c0 + 1] = gv[1];
            pl[(hb +  8) * HP + c0]     = gv[2];
            pl[(hb +  8) * HP + c0 + 1] = gv[3];
            pl[(hb + 16) * HP + c0]     = gv[4];
            pl[(hb + 16) * HP + c0 + 1] = gv[5];
            pl[(hb + 24) * HP + c0]     = gv[6];
            pl[(hb + 24) * HP + c0 + 1] = gv[7];
        }
        __syncthreads();

        // ---- 2. c/h update (1024 items / 512 threads); h -> f32 + B-frag bf16 ----
        #pragma unroll
        for (int q = 0; q < 2; q++) {
            int m = q * NTH + tid;
            int hid = m & (HID - 1), b = m >> 7;
            float gi = smf[FI_GPL + 0 * GPL + hid * HP + b];
            float gf = smf[FI_GPL + 1 * GPL + hid * HP + b];
            float gg = smf[FI_GPL + 2 * GPL + hid * HP + b];
            float go = smf[FI_GPL + 3 * GPL + hid * HP + b];
            float c = fmaf(gf, creg[q], gi * gg);    // gates already activated
            creg[q] = c;
            float h = go * tanh_ap(c);
            smf[FI_H + hid * HP + b] = h;
            // B fragment layout: ks=k>>4, k2=k&15: reg=(k2>>3), tid_g=(k2&7)>>1, hilo=k2&1
            int ks = hid >> 4, k2 = hid & 15;
            uint32_t ba = (uint32_t)O_BF + ks * 256 + (k2 >> 3) * 128
                        + (b * 4 + ((k2 & 7) >> 1)) * 4 + (k2 & 1) * 2;
            *(__nv_bfloat16*)(smem + ba) = __float2bfloat16(h);
        }
        __syncthreads();

        // ---- 3. MMA for gates(t+1): all 16 warps ----
        if (t + 1 < T) {
            #pragma unroll
            for (int u = 0; u < 4; u++) { acc0[u] = 0.f; acc1[u] = 0.f; }
            #pragma unroll
            for (int ks = 0; ks < 8; ks++) {
                uint32_t a0[4], a1[4];
                ldsm4(a0, aA0 + ks * 32);
                ldsm4(a1, aA1 + ks * 32);
                uint32_t b0 = *(const uint32_t*)(smem + (aB - sb) + ks * 256);
                uint32_t b1 = *(const uint32_t*)(smem + (aB - sb) + ks * 256 + 128);
                mma16816(acc0, a0, b0, b1);
                mma16816(acc1, a1, b0, b1);
            }
        }

        // ---- 4. Kalman C phase (warps 0..7): sigma-FC + Q-adapt + update + predict ----
        if (wid < NB) {
            float sg = 0.0f;
            if (lane < 10) {
                const float* wf = &smf[FI_WFCP + lane * 132];
                float q0 = smf[FI_BFC + lane], q1 = 0.f, q2 = 0.f, q3 = 0.f;
                #pragma unroll
                for (int k = 0; k < HID; k += 4) {
                    q0 = fmaf(smf[FI_H + (k + 0) * HP + wid], wf[k + 0], q0);
                    q1 = fmaf(smf[FI_H + (k + 1) * HP + wid], wf[k + 1], q1);
                    q2 = fmaf(smf[FI_H + (k + 2) * HP + wid], wf[k + 2], q2);
                    q3 = fmaf(smf[FI_H + (k + 3) * HP + wid], wf[k + 3], q3);
                }
                sg = sigm((q0 + q1) + (q2 + q3));
            }
            float Ppl = Pp;
            #pragma unroll
            for (int n = 0; n < 10; n++) {
                float sn = __shfl_sync(FULL, sg, n);
                Ppl = fmaf(sn, smf[FI_QT + n * 16 + (lane & 15)], Ppl);
            }
            float s00 = __shfl_sync(FULL, Ppl, 0) + RV;
            float s01 = __shfl_sync(FULL, Ppl, 1);
            float s10 = __shfl_sync(FULL, Ppl, 4);
            float s11 = __shfl_sync(FULL, Ppl, 5) + RV;
            float rdet = 1.0f / (s00 * s11 - s01 * s10);
            int i4 = lane & 12, j = lane & 3;
            float Pp4i  = __shfl_sync(FULL, Ppl, i4);
            float Pp4i1 = __shfl_sync(FULL, Ppl, i4 + 1);
            float Ppj   = __shfl_sync(FULL, Ppl, j);
            float Pp4j  = __shfl_sync(FULL, Ppl, 4 + j);
            float K0 = (Pp4i * s11 - Pp4i1 * s10) * rdet;
            float K1 = (Pp4i1 * s00 - Pp4i * s01) * rdet;
            P = Ppl - K0 * Ppj - K1 * Pp4j;
            float xpi = (lane >= 8) ? ((lane >= 12) ? xp3 : xp2)
                                    : ((lane >= 4) ? xp1 : xp0);
            float xn = xpi + K0 * iv0 + K1 * iv1;
            if ((lane & 3) == 0 && lane < 16)
                out[((size_t)gb * T + t) * 4 + (lane >> 2)] = xn;
            x0 = __shfl_sync(FULL, xn, 0);
            x1 = __shfl_sync(FULL, xn, 4);
            x2 = __shfl_sync(FULL, xn, 8);
            x3 = __shfl_sync(FULL, xn, 12);
            kpredict(Pp, xp0, xp1, xp2, xp3, iv0, iv1, P, x0, x1, x2, x3,
                     meas, smf, gb, t + 1, T, lane, wid);
        }
        __syncthreads();
    }
}

extern "C" void kernel_launch(void* const* d_in, const int* in_sizes, int n_in,
                              void* d_out, int out_size) {
    const float* meas = (const float*)d_in[0];
    const float* Qt   = (const float*)d_in[1];
    const float* Wih  = (const float*)d_in[2];
    const float* Whh  = (const float*)d_in[3];
    const float* bih  = (const float*)d_in[4];
    const float* bhh  = (const float*)d_in[5];
    const float* Wfc  = (const float*)d_in[6];
    const float* bfc  = (const float*)d_in[7];
    float* out = (float*)d_out;
    int T = in_sizes[0] / (BATCH * 2);

    cudaFuncSetAttribute(nnakf_kernel,
                         cudaFuncAttributeMaxDynamicSharedMemorySize, SMEM_BYTES);
    nnakf_kernel<<<BATCH / NB, NTH, SMEM_BYTES>>>(
        meas, Qt, Wih, Whh, bih, bhh, Wfc, bfc, out, T);
}

// round 5
// speedup vs baseline: 4.7297x; 1.2319x over previous
#include <cuda_runtime.h>
#include <cuda_bf16.h>
#include <cstdint>

#define BATCH 1024
#define NB 8            // batches per CTA (MMA N)
#define NTH 512         // 16 warps
#define HID 128
#define G4  512
#define DTC 0.1f
#define Q0V 0.01f
#define RV  0.25f
#define FULL 0xffffffffu
#define AST 272         // Whh bf16 row stride in bytes (conflict-free LDSM)
#define HTS 132         // h_t row stride (floats): conflict-free + 16B aligned

// ---- byte offsets in dynamic smem ----
#define O_A     0         // Whh bf16 [512 rows x 272B], gate-permuted = 139264
#define O_BF    139264    // B fragments (h bf16), 8 ksteps x 256B = 2048
#define O_HT    141312    // h f32 [b][k], 8 x 132 floats = 4224
#define O_WFCP  145536    // 10 x 132 floats = 5280
#define O_QT    150816    // 160 floats = 640
#define O_IN    151456    // 16 floats = 64
#define O_BFC   151520    // 10 floats = 40
#define SMEM_BYTES 151584

#define FI_HT   (O_HT / 4)
#define FI_WFCP (O_WFCP / 4)
#define FI_QT   (O_QT / 4)
#define FI_IN   (O_IN / 4)
#define FI_BFC  (O_BFC / 4)

__device__ __forceinline__ uint32_t smem_u32(const void* p) {
    uint32_t a;
    asm("{ .reg .u64 t; cvta.to.shared.u64 t, %1; cvt.u32.u64 %0, t; }" : "=r"(a) : "l"(p));
    return a;
}
__device__ __forceinline__ float tanh_ap(float x) {
    float y; asm("tanh.approx.f32 %0, %1;" : "=f"(y) : "f"(x)); return y;
}
__device__ __forceinline__ float sigm(float x) {
    return fmaf(tanh_ap(0.5f * x), 0.5f, 0.5f);
}
__device__ __forceinline__ void ldsm4(uint32_t* a, uint32_t addr) {
    asm volatile("ldmatrix.sync.aligned.m8n8.x4.shared.b16 {%0,%1,%2,%3}, [%4];"
                 : "=r"(a[0]), "=r"(a[1]), "=r"(a[2]), "=r"(a[3]) : "r"(addr));
}
__device__ __forceinline__ void mma16816(float* c, const uint32_t* a, uint32_t b0, uint32_t b1) {
    asm volatile(
        "mma.sync.aligned.m16n8k16.row.col.f32.bf16.bf16.f32 "
        "{%0,%1,%2,%3}, {%4,%5,%6,%7}, {%8,%9}, {%0,%1,%2,%3};"
        : "+f"(c[0]), "+f"(c[1]), "+f"(c[2]), "+f"(c[3])
        : "r"(a[0]), "r"(a[1]), "r"(a[2]), "r"(a[3]), "r"(b0), "r"(b1));
}

// Warp-parallel Kalman predict + innovation (warp = one batch, lane e<16 = P elem e)
__device__ __forceinline__ void kpredict(
    float& Pp, float& xp0, float& xp1, float& xp2, float& xp3,
    float& iv0, float& iv1,
    float P, float x0, float x1, float x2, float x3,
    const float* __restrict__ meas, float* smf,
    size_t gb, int t, int T, int lane, int b)
{
    xp0 = fmaf(DTC, x2, x0); xp1 = fmaf(DTC, x3, x1); xp2 = x2; xp3 = x3;
    float P8 = __shfl_down_sync(FULL, P, 8);
    float A  = (lane < 8) ? fmaf(DTC, P8, P) : P;
    float A2 = __shfl_down_sync(FULL, A, 2);
    float Ppv = ((lane & 3) < 2) ? fmaf(DTC, A2, A) : A;
    if (lane == 0 || lane == 5 || lane == 10 || lane == 15) Ppv += Q0V;
    Pp = Ppv;
    if (t < T) {
        float2 z = *(const float2*)(meas + ((size_t)gb * T + t) * 2);
        iv0 = z.x - xp0; iv1 = z.y - xp1;
        float Pp0 = __shfl_sync(FULL, Ppv, 0);
        float Pp5 = __shfl_sync(FULL, Ppv, 5);
        if (lane == 0) {
            smf[FI_IN + 2 * b]     = iv0 * iv0 / (Pp0 + RV);
            smf[FI_IN + 2 * b + 1] = iv1 * iv1 / (Pp5 + RV);
        }
    }
}

__global__ void __launch_bounds__(NTH, 1) nnakf_kernel(
    const float* __restrict__ meas, const float* __restrict__ Qt,
    const float* __restrict__ Wih,  const float* __restrict__ Whh,
    const float* __restrict__ bih,  const float* __restrict__ bhh,
    const float* __restrict__ Wfc,  const float* __restrict__ bfc,
    float* __restrict__ out, int T)
{
    extern __shared__ char smem[];
    float* smf = (float*)smem;
    const uint32_t sb = smem_u32(smem);
    const int tid  = threadIdx.x;
    const int wid  = tid >> 5;
    const int lane = tid & 31;
    const int g    = lane >> 2, tq = lane & 3;

    // ---- one-time staging: Whh gate-permuted so warp owns all 4 gates ----
    // orig row R = gate*128 + hid  ->  staged row (hid>>3)*32 + gate*8 + (hid&7)
    for (int idx = tid; idx < G4 * HID; idx += NTH) {
        int R = idx >> 7, k = idx & 127;
        int gate = R >> 7, hid = R & 127;
        int Rst = (hid >> 3) * 32 + gate * 8 + (hid & 7);
        *(__nv_bfloat16*)(smem + O_A + Rst * AST + k * 2) = __float2bfloat16(Whh[idx]);
    }
    for (int idx = tid; idx < 10 * HID; idx += NTH) {
        int n = idx >> 7, k = idx & 127;
        smf[FI_WFCP + n * HTS + k] = Wfc[idx];
    }
    for (int idx = tid; idx < 160; idx += NTH) smf[FI_QT + idx] = Qt[idx];
    if (tid < 10) smf[FI_BFC + tid] = bfc[tid];

    // ---- per-thread epilogue constants (hid = wid*8+g, gates o=0..3) ----
    const int hid = wid * 8 + g;
    float bia[4], wa[4], wb[4];
    #pragma unroll
    for (int o = 0; o < 4; o++) {
        int R = o * HID + hid;
        bia[o] = bih[R] + bhh[R];
        wa[o]  = Wih[2 * R];
        wb[o]  = Wih[2 * R + 1];
    }
    // LDSM base addresses (invariant)
    const int r_lds = wid * 32 + (lane & 7) + ((lane >> 3) & 1) * 8;
    const uint32_t aA0 = sb + O_A + r_lds * AST + (lane >> 4) * 16;
    const uint32_t aA1 = aA0 + 16 * AST;
    const uint32_t aB  = sb + O_BF + lane * 4;

    // B-frag store address for (hid, b0=2tq)
    const int ksh = hid >> 4, k2 = hid & 15;
    const uint32_t bfa = (uint32_t)O_BF + ksh * 256 + (k2 >> 3) * 128
                       + ((2 * tq) * 4 + ((k2 & 7) >> 1)) * 4 + (k2 & 1) * 2;

    float acc0[4] = {0.f, 0.f, 0.f, 0.f}, acc1[4] = {0.f, 0.f, 0.f, 0.f};
    float c0 = 0.f, c1 = 0.f;                    // LSTM cell state in registers

    // ---- Kalman lane state (warps 0..7) ----
    float P = (lane == 0 || lane == 5 || lane == 10 || lane == 15) ? 1.0f : 0.0f;
    float x0 = 0.f, x1 = 0.f, x2 = 0.f, x3 = 0.f;
    float Pp = 0.f, xp0 = 0.f, xp1 = 0.f, xp2 = 0.f, xp3 = 0.f, iv0 = 0.f, iv1 = 0.f;
    const size_t gb = (size_t)blockIdx.x * NB + wid;

    if (wid < NB)
        kpredict(Pp, xp0, xp1, xp2, xp3, iv0, iv1, P, x0, x1, x2, x3,
                 meas, smf, gb, 0, T, lane, wid);
    __syncthreads();   // In(0) + weights visible; accs=0 == gates from h0=0

    for (int t = 0; t < T; t++) {
        // ---- E: epilogue + LSTM cell, all in registers; store h (bf16 frag + f32) ----
        {
            float4 inv = *(const float4*)&smf[FI_IN + 4 * tq];
            float gi0 = sigm(fmaf(wa[0], inv.x, fmaf(wb[0], inv.y, acc0[0] + bia[0])));
            float gi1 = sigm(fmaf(wa[0], inv.z, fmaf(wb[0], inv.w, acc0[1] + bia[0])));
            float gf0 = sigm(fmaf(wa[1], inv.x, fmaf(wb[1], inv.y, acc0[2] + bia[1])));
            float gf1 = sigm(fmaf(wa[1], inv.z, fmaf(wb[1], inv.w, acc0[3] + bia[1])));
            float gg0 = tanh_ap(fmaf(wa[2], inv.x, fmaf(wb[2], inv.y, acc1[0] + bia[2])));
            float gg1 = tanh_ap(fmaf(wa[2], inv.z, fmaf(wb[2], inv.w, acc1[1] + bia[2])));
            float go0 = sigm(fmaf(wa[3], inv.x, fmaf(wb[3], inv.y, acc1[2] + bia[3])));
            float go1 = sigm(fmaf(wa[3], inv.z, fmaf(wb[3], inv.w, acc1[3] + bia[3])));
            c0 = fmaf(gf0, c0, gi0 * gg0);
            c1 = fmaf(gf1, c1, gi1 * gg1);
            float h0 = go0 * tanh_ap(c0);
            float h1 = go1 * tanh_ap(c1);
            smf[FI_HT + (2 * tq) * HTS + hid]     = h0;
            smf[FI_HT + (2 * tq + 1) * HTS + hid] = h1;
            *(__nv_bfloat16*)(smem + bfa)      = __float2bfloat16(h0);
            *(__nv_bfloat16*)(smem + bfa + 16) = __float2bfloat16(h1);
        }
        __syncthreads();

        // ---- M: MMA for gates(t+1) (all 16 warps) ----
        if (t + 1 < T) {
            #pragma unroll
            for (int u = 0; u < 4; u++) { acc0[u] = 0.f; acc1[u] = 0.f; }
            #pragma unroll
            for (int ks = 0; ks < 8; ks++) {
                uint32_t a0[4], a1[4];
                ldsm4(a0, aA0 + ks * 32);
                ldsm4(a1, aA1 + ks * 32);
                uint32_t b0 = *(const uint32_t*)(smem + (aB - sb) + ks * 256);
                uint32_t b1 = *(const uint32_t*)(smem + (aB - sb) + ks * 256 + 128);
                mma16816(acc0, a0, b0, b1);
                mma16816(acc1, a1, b0, b1);
            }
        }

        // ---- M: Kalman C phase (warps 0..7) ----
        if (wid < NB) {
            float sg = 0.0f;
            if (lane < 10) {
                const float4* wf = (const float4*)&smf[FI_WFCP + lane * HTS];
                const float4* hh = (const float4*)&smf[FI_HT + wid * HTS];
                float q0 = smf[FI_BFC + lane], q1 = 0.f, q2 = 0.f, q3 = 0.f;
                #pragma unroll
                for (int kc = 0; kc < HID / 4; kc++) {
                    float4 w4 = wf[kc], h4 = hh[kc];
                    q0 = fmaf(w4.x, h4.x, q0); q1 = fmaf(w4.y, h4.y, q1);
                    q2 = fmaf(w4.z, h4.z, q2); q3 = fmaf(w4.w, h4.w, q3);
                }
                sg = sigm((q0 + q1) + (q2 + q3));
            }
            float Ppl = Pp;
            #pragma unroll
            for (int n = 0; n < 10; n++) {
                float sn = __shfl_sync(FULL, sg, n);
                Ppl = fmaf(sn, smf[FI_QT + n * 16 + (lane & 15)], Ppl);
            }
            float s00 = __shfl_sync(FULL, Ppl, 0) + RV;
            float s01 = __shfl_sync(FULL, Ppl, 1);
            float s10 = __shfl_sync(FULL, Ppl, 4);
            float s11 = __shfl_sync(FULL, Ppl, 5) + RV;
            float rdet = 1.0f / (s00 * s11 - s01 * s10);
            int i4 = lane & 12, j = lane & 3;
            float Pp4i  = __shfl_sync(FULL, Ppl, i4);
            float Pp4i1 = __shfl_sync(FULL, Ppl, i4 + 1);
            float Ppj   = __shfl_sync(FULL, Ppl, j);
            float Pp4j  = __shfl_sync(FULL, Ppl, 4 + j);
            float K0 = (Pp4i * s11 - Pp4i1 * s10) * rdet;
            float K1 = (Pp4i1 * s00 - Pp4i * s01) * rdet;
            P = Ppl - K0 * Ppj - K1 * Pp4j;
            float xpi = (lane >= 8) ? ((lane >= 12) ? xp3 : xp2)
                                    : ((lane >= 4) ? xp1 : xp0);
            float xn = xpi + K0 * iv0 + K1 * iv1;
            if ((lane & 3) == 0 && lane < 16)
                out[((size_t)gb * T + t) * 4 + (lane >> 2)] = xn;
            x0 = __shfl_sync(FULL, xn, 0);
            x1 = __shfl_sync(FULL, xn, 4);
            x2 = __shfl_sync(FULL, xn, 8);
            x3 = __shfl_sync(FULL, xn, 12);
            kpredict(Pp, xp0, xp1, xp2, xp3, iv0, iv1, P, x0, x1, x2, x3,
                     meas, smf, gb, t + 1, T, lane, wid);
        }
        __syncthreads();
    }
}

extern "C" void kernel_launch(void* const* d_in, const int* in_sizes, int n_in,
                              void* d_out, int out_size) {
    const float* meas = (const float*)d_in[0];
    const float* Qt   = (const float*)d_in[1];
    const float* Wih  = (const float*)d_in[2];
    const float* Whh  = (const float*)d_in[3];
    const float* bih  = (const float*)d_in[4];
    const float* bhh  = (const float*)d_in[5];
    const float* Wfc  = (const float*)d_in[6];
    const float* bfc  = (const float*)d_in[7];
    float* out = (float*)d_out;
    int T = in_sizes[0] / (BATCH * 2);

    cudaFuncSetAttribute(nnakf_kernel,
                         cudaFuncAttributeMaxDynamicSharedMemorySize, SMEM_BYTES);
    nnakf_kernel<<<BATCH / NB, NTH, SMEM_BYTES>>>(
        meas, Qt, Wih, Whh, bih, bhh, Wfc, bfc, out, T);
}

// round 7
// speedup vs baseline: 6.2667x; 1.3250x over previous
#include <cuda_runtime.h>
#include <cuda_bf16.h>
#include <cstdint>

#define BATCH 1024
#define NB 8            // batches per CTA (MMA N)
#define NTH 512         // 16 warps
#define HID 128
#define G4  512
#define DTC 0.1f
#define Q0V 0.01f
#define RV  0.25f
#define FULL 0xffffffffu
#define AST 272         // Whh bf16 row stride in bytes (conflict-free LDSM at init)
#define HTS 132         // h_t / Wfc row stride (floats): conflict-free + 16B aligned

// ---- byte offsets in dynamic smem ----
#define O_A     0         // Whh bf16 [512 rows x 272B], gate-permuted = 139264 (init only)
#define O_BF    139264    // B fragments (h bf16), 8 ksteps x 256B = 2048
#define O_HT    141312    // h f32 [b][k], 8 x 132 floats = 4224
#define O_WFCP  145536    // 10 x 132 floats = 5280
#define O_QT    150816    // 160 floats = 640
#define O_IN    151456    // 16 floats = 64
#define O_BFC   151520    // 10 floats = 40
#define O_SIG   151560    // 80 floats = 320
#define SMEM_BYTES 151880

#define FI_HT   (O_HT / 4)
#define FI_WFCP (O_WFCP / 4)
#define FI_QT   (O_QT / 4)
#define FI_IN   (O_IN / 4)
#define FI_BFC  (O_BFC / 4)
#define FI_SIG  (O_SIG / 4)

#define BAR_SYNC(id, cnt)   asm volatile("bar.sync %0, %1;"   :: "r"(id), "r"(cnt) : "memory")
#define BAR_ARRIVE(id, cnt) asm volatile("bar.arrive %0, %1;" :: "r"(id), "r"(cnt) : "memory")

__device__ __forceinline__ uint32_t smem_u32(const void* p) {
    uint32_t a;
    asm("{ .reg .u64 t; cvta.to.shared.u64 t, %1; cvt.u32.u64 %0, t; }" : "=r"(a) : "l"(p));
    return a;
}
__device__ __forceinline__ float tanh_ap(float x) {
    float y; asm("tanh.approx.f32 %0, %1;" : "=f"(y) : "f"(x)); return y;
}
__device__ __forceinline__ float sigm(float x) {
    return fmaf(tanh_ap(0.5f * x), 0.5f, 0.5f);
}
__device__ __forceinline__ void ldsm4(uint32_t* a, uint32_t addr) {
    asm volatile("ldmatrix.sync.aligned.m8n8.x4.shared.b16 {%0,%1,%2,%3}, [%4];"
                 : "=r"(a[0]), "=r"(a[1]), "=r"(a[2]), "=r"(a[3]) : "r"(addr));
}
__device__ __forceinline__ void mma16816(float* c, const uint32_t* a, uint32_t b0, uint32_t b1) {
    asm volatile(
        "mma.sync.aligned.m16n8k16.row.col.f32.bf16.bf16.f32 "
        "{%0,%1,%2,%3}, {%4,%5,%6,%7}, {%8,%9}, {%0,%1,%2,%3};"
        : "+f"(c[0]), "+f"(c[1]), "+f"(c[2]), "+f"(c[3])
        : "r"(a[0]), "r"(a[1]), "r"(a[2]), "r"(a[3]), "r"(b0), "r"(b1));
}

// Warp-parallel Kalman predict + innovation (warp = one batch, lane e<16 = P elem e)
__device__ __forceinline__ void kpredict(
    float& Pp, float& xp0, float& xp1, float& xp2, float& xp3,
    float& iv0, float& iv1,
    float P, float x0, float x1, float x2, float x3,
    float2 z, float* smf, int lane, int b)
{
    xp0 = fmaf(DTC, x2, x0); xp1 = fmaf(DTC, x3, x1); xp2 = x2; xp3 = x3;
    float P8 = __shfl_down_sync(FULL, P, 8);
    float A  = (lane < 8) ? fmaf(DTC, P8, P) : P;
    float A2 = __shfl_down_sync(FULL, A, 2);
    float Ppv = ((lane & 3) < 2) ? fmaf(DTC, A2, A) : A;
    if (lane == 0 || lane == 5 || lane == 10 || lane == 15) Ppv += Q0V;
    Pp = Ppv;
    iv0 = z.x - xp0; iv1 = z.y - xp1;
    float Pp0 = __shfl_sync(FULL, Ppv, 0);
    float Pp5 = __shfl_sync(FULL, Ppv, 5);
    if (lane == 0) {
        smf[FI_IN + 2 * b]     = iv0 * iv0 / (Pp0 + RV);
        smf[FI_IN + 2 * b + 1] = iv1 * iv1 / (Pp5 + RV);
    }
}

__global__ void __launch_bounds__(NTH, 1) nnakf_kernel(
    const float* __restrict__ meas, const float* __restrict__ Qt,
    const float* __restrict__ Wih,  const float* __restrict__ Whh,
    const float* __restrict__ bih,  const float* __restrict__ bhh,
    const float* __restrict__ Wfc,  const float* __restrict__ bfc,
    float* __restrict__ out, int T)
{
    extern __shared__ char smem[];
    float* smf = (float*)smem;
    const uint32_t sb = smem_u32(smem);
    const int tid  = threadIdx.x;
    const int wid  = tid >> 5;
    const int lane = tid & 31;
    const int g    = lane >> 2, tq = lane & 3;

    // ---- one-time staging: Whh gate-permuted so each warp owns all 4 gates ----
    // orig row R = gate*128 + hid  ->  staged row (hid>>3)*32 + gate*8 + (hid&7)
    for (int idx = tid; idx < G4 * HID; idx += NTH) {
        int R = idx >> 7, k = idx & 127;
        int gate = R >> 7, hh = R & 127;
        int Rst = (hh >> 3) * 32 + gate * 8 + (hh & 7);
        *(__nv_bfloat16*)(smem + O_A + Rst * AST + k * 2) = __float2bfloat16(Whh[idx]);
    }
    for (int idx = tid; idx < 10 * HID; idx += NTH) {
        int n = idx >> 7, k = idx & 127;
        smf[FI_WFCP + n * HTS + k] = Wfc[idx];
    }
    for (int idx = tid; idx < 160; idx += NTH) smf[FI_QT + idx] = Qt[idx];
    if (tid < 10) smf[FI_BFC + tid] = bfc[tid];

    // ---- per-thread epilogue constants (hid = wid*8+g, gate o = 0..3) ----
    const int hid = wid * 8 + g;
    float bia[4], wa[4], wb[4];
    #pragma unroll
    for (int o = 0; o < 4; o++) {
        int R = o * HID + hid;
        bia[o] = bih[R] + bhh[R];
        wa[o]  = Wih[2 * R];
        wb[o]  = Wih[2 * R + 1];
    }
    __syncthreads();

    // ---- A fragments -> registers (time-invariant!) ----
    const int r_lds = wid * 32 + (lane & 7) + ((lane >> 3) & 1) * 8;
    const uint32_t aA0 = sb + O_A + r_lds * AST + (lane >> 4) * 16;
    const uint32_t aA1 = aA0 + 16 * AST;
    uint32_t aF0[8][4], aF1[8][4];
    #pragma unroll
    for (int ks = 0; ks < 8; ks++) {
        ldsm4(aF0[ks], aA0 + ks * 32);
        ldsm4(aF1[ks], aA1 + ks * 32);
    }

    // B-frag store address for (hid, n=2tq): layout addr = ks*256 + (n*4+tg)*8 + hi*4 + lo*2
    const int ksh = hid >> 4, k2 = hid & 15, tg = (k2 & 7) >> 1, hi = k2 >> 3, lo = k2 & 1;
    const uint32_t bfa = (uint32_t)O_BF + ksh * 256 + ((2 * tq) * 4 + tg) * 8 + hi * 4 + lo * 2;

    float acc0[4] = {0.f, 0.f, 0.f, 0.f}, acc1[4] = {0.f, 0.f, 0.f, 0.f};
    float c0 = 0.f, c1 = 0.f;                    // LSTM cell state in registers

    // ---- Kalman lane state (warps 0..7) ----
    float P = (lane == 0 || lane == 5 || lane == 10 || lane == 15) ? 1.0f : 0.0f;
    float x0 = 0.f, x1 = 0.f, x2 = 0.f, x3 = 0.f;
    float Pp = 0.f, xp0 = 0.f, xp1 = 0.f, xp2 = 0.f, xp3 = 0.f, iv0 = 0.f, iv1 = 0.f;
    const size_t gb = (size_t)blockIdx.x * NB + wid;

    if (wid < NB) {
        float2 z0 = *(const float2*)(meas + (size_t)gb * T * 2);
        kpredict(Pp, xp0, xp1, xp2, xp3, iv0, iv1, P, x0, x1, x2, x3,
                 z0, smf, lane, wid);
    }
    __syncthreads();   // In(0) visible; accs=0 == gates from h0=0

    for (int t = 0; t < T; t++) {
        // ---- E: epilogue + LSTM cell in registers; store h (f32 + bf16 B-frag) ----
        {
            float4 inv = *(const float4*)&smf[FI_IN + 4 * tq];
            float gi0 = sigm(fmaf(wa[0], inv.x, fmaf(wb[0], inv.y, acc0[0] + bia[0])));
            float gi1 = sigm(fmaf(wa[0], inv.z, fmaf(wb[0], inv.w, acc0[1] + bia[0])));
            float gf0 = sigm(fmaf(wa[1], inv.x, fmaf(wb[1], inv.y, acc0[2] + bia[1])));
            float gf1 = sigm(fmaf(wa[1], inv.z, fmaf(wb[1], inv.w, acc0[3] + bia[1])));
            float gg0 = tanh_ap(fmaf(wa[2], inv.x, fmaf(wb[2], inv.y, acc1[0] + bia[2])));
            float gg1 = tanh_ap(fmaf(wa[2], inv.z, fmaf(wb[2], inv.w, acc1[1] + bia[2])));
            float go0 = sigm(fmaf(wa[3], inv.x, fmaf(wb[3], inv.y, acc1[2] + bia[3])));
            float go1 = sigm(fmaf(wa[3], inv.z, fmaf(wb[3], inv.w, acc1[3] + bia[3])));
            c0 = fmaf(gf0, c0, gi0 * gg0);
            c1 = fmaf(gf1, c1, gi1 * gg1);
            float h0 = go0 * tanh_ap(c0);
            float h1 = go1 * tanh_ap(c1);
            smf[FI_HT + (2 * tq) * HTS + hid]     = h0;
            smf[FI_HT + (2 * tq + 1) * HTS + hid] = h1;
            *(__nv_bfloat16*)(smem + bfa)      = __float2bfloat16(h0);
            *(__nv_bfloat16*)(smem + bfa + 32) = __float2bfloat16(h1);   // n+1
        }
        __syncthreads();

        // ---- M: prefetch z(t+1), MMA for gates(t+1), split sigma/Kalman ----
        float2 zn = make_float2(0.f, 0.f);
        if (wid < NB && t + 1 < T)
            zn = *(const float2*)(meas + ((size_t)gb * T + t + 1) * 2);

        if (t + 1 < T) {
            #pragma unroll
            for (int u = 0; u < 4; u++) { acc0[u] = 0.f; acc1[u] = 0.f; }
            #pragma unroll
            for (int ks = 0; ks < 8; ks++) {
                uint2 bb = *(const uint2*)(smem + O_BF + ks * 256 + lane * 8);
                mma16816(acc0, aF0[ks], bb.x, bb.y);
                mma16816(acc1, aF1[ks], bb.x, bb.y);
            }
        }

        if (wid >= NB) {
            // ---- sigma-FC for batch (wid-8): 2 lanes per FC row ----
            const int b = wid - NB;
            const int n = lane >> 1, s = lane & 1;
            float sg = 0.0f;
            if (lane < 20) {
                const float4* wf = (const float4*)&smf[FI_WFCP + n * HTS + s * 64];
                const float4* hh = (const float4*)&smf[FI_HT + b * HTS + s * 64];
                float q0 = 0.f, q1 = 0.f, q2 = 0.f, q3 = 0.f;
                #pragma unroll
                for (int kc = 0; kc < 16; kc++) {
                    float4 w4 = wf[kc], h4 = hh[kc];
                    q0 = fmaf(w4.x, h4.x, q0); q1 = fmaf(w4.y, h4.y, q1);
                    q2 = fmaf(w4.z, h4.z, q2); q3 = fmaf(w4.w, h4.w, q3);
                }
                sg = (q0 + q1) + (q2 + q3);
            }
            sg += __shfl_xor_sync(FULL, sg, 1);
            if (lane < 20 && s == 0)
                smf[FI_SIG + b * 10 + n] = sigm(sg + smf[FI_BFC + n]);
            BAR_ARRIVE(1, NTH);
        } else {
            // ---- Kalman C phase (warps 0..7) ----
            BAR_SYNC(1, NTH);    // wait for sigma
            float Ppl = Pp;
            #pragma unroll
            for (int n = 0; n < 10; n++)
                Ppl = fmaf(smf[FI_SIG + wid * 10 + n],
                           smf[FI_QT + n * 16 + (lane & 15)], Ppl);
            float s00 = __shfl_sync(FULL, Ppl, 0) + RV;
            float s01 = __shfl_sync(FULL, Ppl, 1);
            float s10 = __shfl_sync(FULL, Ppl, 4);
            float s11 = __shfl_sync(FULL, Ppl, 5) + RV;
            float rdet = 1.0f / (s00 * s11 - s01 * s10);
            int i4 = lane & 12, j = lane & 3;
            float Pp4i  = __shfl_sync(FULL, Ppl, i4);
            float Pp4i1 = __shfl_sync(FULL, Ppl, i4 + 1);
            float Ppj   = __shfl_sync(FULL, Ppl, j);
            float Pp4j  = __shfl_sync(FULL, Ppl, 4 + j);
            float K0 = (Pp4i * s11 - Pp4i1 * s10) * rdet;
            float K1 = (Pp4i1 * s00 - Pp4i * s01) * rdet;
            P = Ppl - K0 * Ppj - K1 * Pp4j;
            float xpi = (lane >= 8) ? ((lane >= 12) ? xp3 : xp2)
                                    : ((lane >= 4) ? xp1 : xp0);
            float xn = xpi + K0 * iv0 + K1 * iv1;
            x0 = __shfl_sync(FULL, xn, 0);
            x1 = __shfl_sync(FULL, xn, 4);
            x2 = __shfl_sync(FULL, xn, 8);
            x3 = __shfl_sync(FULL, xn, 12);
            if (lane == 0)
                *(float4*)(out + ((size_t)gb * T + t) * 4) = make_float4(x0, x1, x2, x3);
            kpredict(Pp, xp0, xp1, xp2, xp3, iv0, iv1, P, x0, x1, x2, x3,
                     zn, smf, lane, wid);
        }
        __syncthreads();
    }
}

extern "C" void kernel_launch(void* const* d_in, const int* in_sizes, int n_in,
                              void* d_out, int out_size) {
    const float* meas = (const float*)d_in[0];
    const float* Qt   = (const float*)d_in[1];
    const float* Wih  = (const float*)d_in[2];
    const float* Whh  = (const float*)d_in[3];
    const float* bih  = (const float*)d_in[4];
    const float* bhh  = (const float*)d_in[5];
    const float* Wfc  = (const float*)d_in[6];
    const float* bfc  = (const float*)d_in[7];
    float* out = (float*)d_out;
    int T = in_sizes[0] / (BATCH * 2);

    cudaFuncSetAttribute(nnakf_kernel,
                         cudaFuncAttributeMaxDynamicSharedMemorySize, SMEM_BYTES);
    nnakf_kernel<<<BATCH / NB, NTH, SMEM_BYTES>>>(
        meas, Qt, Wih, Whh, bih, bhh, Wfc, bfc, out, T);
}